// round 10
// baseline (speedup 1.0000x reference)
#include <cuda_runtime.h>
#include <cstdint>

#define NB 64
#define NT 4096
#define NS 64

__device__ __forceinline__ void fma2(unsigned long long &d, unsigned long long a, unsigned long long b) {
    asm("fma.rn.f32x2 %0, %1, %2, %0;" : "+l"(d) : "l"(a), "l"(b));
}
__device__ __forceinline__ unsigned long long add2(unsigned long long a, unsigned long long b) {
    unsigned long long d;
    asm("add.rn.f32x2 %0, %1, %2;" : "=l"(d) : "l"(a), "l"(b));
    return d;
}
__device__ __forceinline__ unsigned long long pk2(float lo, float hi) {
    unsigned long long d;
    asm("mov.b64 %0, {%1, %2};" : "=l"(d) : "f"(lo), "f"(hi));
    return d;
}

__global__ __launch_bounds__(NS, 1) void hmm_forward_kernel(
    const float* __restrict__ trans,   // (S,S)
    const float* __restrict__ emis,    // (B,T,S)
    float* __restrict__ alpha_out,     // (B,T,S)
    float* __restrict__ logz_out)      // (B,)
{
    const int b = blockIdx.x;
    const int j = threadIdx.x;      // state index 0..63

    __shared__ __align__(16) float su[2][NS];  // u = exp(alpha - N), parity double-buffered
    __shared__ float ring[4];                  // r_t = alpha_t[0] ring (normalizer source)

    // exp(transition) column j as packed f32x2 pairs: eA[k] = (e^A[2k][j], e^A[2k+1][j])
    unsigned long long eA[NS / 2];
#pragma unroll
    for (int k = 0; k < NS / 2; k++) {
        float e0 = __expf(trans[(2 * k) * NS + j]);
        float e1 = __expf(trans[(2 * k + 1) * NS + j]);
        eA[k] = pk2(e0, e1);
    }

    const float* eb = emis + (size_t)b * NT * NS;
    float* ob = alpha_out + (size_t)b * NT * NS;

    // --- t = 0 ---
    float a0 = eb[j];
    ob[j] = a0;
    // Seeds: r_0 = alpha_0[0]; slots 2,3 stand in for r_{-1}, r_{-2} (= alpha_0[0])
    if (j == 0) { ring[0] = a0; ring[2] = a0; ring[3] = a0; }

    // Prefetch emissions e_1..e_4
    float ebuf[4];
#pragma unroll
    for (int p = 0; p < 4; p++) ebuf[p] = eb[(size_t)(1 + p) * NS + j];

    __syncthreads();
    float N0 = ring[0];                // N_0 = alpha_0[0]
    su[0][j] = __expf(a0 - N0);        // u(0) = exp(alpha_0 - N_0)
    float f = __expf(ebuf[0]);         // f_1 = exp(e_1 - dM_1), dM_1 = 0  (N_1 = N_0)
    __syncthreads();

    // --- Main sequential recurrence ---
    // Invariant: u_j(t) = exp(alpha_t[j] - N_t), with N_t = r_{t-2} (2-step-stale scalar).
    // alpha_t[j] = log s_j(t) + N_{t-1} + e_t[j], where N_{t-1} = r_{t-3} = ring[(t+1)&3].
    // This is EXACT: staleness cancels, ring carries true alpha_t[0], no feedback.
#pragma unroll 4
    for (int t = 1; t < NT; t++) {
        const int buf = t & 1;
        // s_j = sum_i u_i(t-1) * e^A[i][j]  -- broadcast LDS.128, packed f32x2 FMAs
        const ulonglong2* sp = reinterpret_cast<const ulonglong2*>(&su[buf ^ 1][0]);
        unsigned long long acc0 = 0ull, acc1 = 0ull, acc2 = 0ull, acc3 = 0ull;
#pragma unroll
        for (int k = 0; k < 8; k++) {
            ulonglong2 qa = sp[2 * k];
            ulonglong2 qb = sp[2 * k + 1];
            fma2(acc0, qa.x, eA[4 * k + 0]);
            fma2(acc1, qa.y, eA[4 * k + 1]);
            fma2(acc2, qb.x, eA[4 * k + 2]);
            fma2(acc3, qb.y, eA[4 * k + 3]);
        }
        unsigned long long sp2 = add2(add2(acc0, acc1), add2(acc2, acc3));
        float lo, hi;
        asm("mov.b64 {%0, %1}, %2;" : "=f"(lo), "=f"(hi) : "l"(sp2));
        float s = lo + hi;

        float u = s * f;               // u(t) = s * f_t  (f_t precomputed last iteration)
        su[buf][j] = u;
        __syncthreads();

        // ---- off-critical-path work ----
        float Nprev = ring[(t + 1) & 3];                  // r_{t-3} = N_{t-1}
        float e_cur = ebuf[(t - 1) & 3];                  // e_t
        float aout = __logf(s) + Nprev + e_cur;           // alpha_t[j], exact
        ob[(size_t)t * NS + j] = aout;
        if (j == 0) ring[t & 3] = aout;                   // publish r_t = alpha_t[0]

        // refill prefetch slot with e_{t+4}
        ebuf[(t - 1) & 3] = (t + 4 < NT) ? eb[(size_t)(t + 4) * NS + j] : 0.0f;

        // f_{t+1} = exp(e_{t+1} - (r_{t-1} - r_{t-2}))  => N_{t+1} = r_{t-1}
        float dM = ring[(t - 1) & 3] - ring[(t - 2) & 3];
        float e_next = ebuf[t & 3];                       // e_{t+1}
        f = __expf(e_next - dM);

        a0 = aout;                                        // carry for final logsumexp
    }

    // --- log_Z = logsumexp over final alpha (one-time, stable) ---
    su[0][j] = a0;
    __syncthreads();
    if (j == 0) {
        float mx = su[0][0];
#pragma unroll
        for (int i = 1; i < NS; i++) mx = fmaxf(mx, su[0][i]);
        float tot = 0.0f;
#pragma unroll
        for (int i = 0; i < NS; i++) tot += __expf(su[0][i] - mx);
        logz_out[b] = mx + __logf(tot);
    }
}

extern "C" void kernel_launch(void* const* d_in, const int* in_sizes, int n_in,
                              void* d_out, int out_size) {
    const float* trans = (const float*)d_in[0];  // (S,S) fp32
    const float* emis  = (const float*)d_in[1];  // (B,T,S) fp32
    // d_in[2] = seq_lens (unused by reference)
    float* alpha = (float*)d_out;                       // (B,T,S)
    float* logz  = alpha + (size_t)NB * NT * NS;        // (B,)
    hmm_forward_kernel<<<NB, NS>>>(trans, emis, alpha, logz);
}